// round 1
// baseline (speedup 1.0000x reference)
#include <cuda_runtime.h>
#include <math.h>

#define HW 65536
#define BATCH 4
#define CCH 64
#define NCHUNK 64

// Scratch pool: 2*SZ2 + 6*SZ + 16384 + 294912 floats
//  SZ = 4*64*65536 = 16777216, SZ2 = 33554432
__device__ float g_pool[168083456];

__device__ __forceinline__ float gelu_f(float v) {
    return 0.5f * v * (1.0f + erff(v * 0.70710678118654752f));
}

// ---------------- LayerNorm over channel dim (per pixel) ----------------
__global__ void ln_kernel(const float* __restrict__ in, const float* __restrict__ w,
                          const float* __restrict__ bb, float* __restrict__ out)
{
    int p = blockIdx.x * blockDim.x + threadIdx.x;  // 0 .. B*HW-1
    int b = p >> 16;
    int pix = p & 65535;
    const float* ip = in + (long)b * (CCH * HW) + pix;
    float s = 0.f, ss = 0.f;
#pragma unroll 8
    for (int c = 0; c < CCH; ++c) {
        float v = ip[(long)c * HW];
        s += v; ss += v * v;
    }
    float mu = s * (1.0f / CCH);
    float var = ss * (1.0f / CCH) - mu * mu;
    float r = rsqrtf(var + 1e-5f);
    float* op = out + (long)b * (CCH * HW) + pix;
#pragma unroll 8
    for (int c = 0; c < CCH; ++c) {
        float v = ip[(long)c * HW];
        op[(long)c * HW] = (v - mu) * r * w[c] + bb[c];
    }
}

// ---------------- 1x1 conv (GEMM over pixels). 128 threads/block. ----------------
// Per thread: 8 output channels x 4 pixels register tile.
template<int OC, bool PBW, bool RES>
__global__ void conv1x1_kernel(const float* __restrict__ in, const float* __restrict__ w,
                               const float* __restrict__ res, float* __restrict__ out,
                               int in_bstride, int ic_off)
{
    constexpr int OCG = OC / 8;            // oc groups
    constexpr int PXT = (128 / OCG) * 4;   // pixel tile
    __shared__ float sW[64 * OC];          // [ic][oc]
    __shared__ float sIn[64 * PXT];        // [ic][px]
    int b = blockIdx.y;
    int pix0 = blockIdx.x * PXT;
    int tid = threadIdx.x;
    const float* wb = PBW ? (w + b * 64 * OC) : w;
    for (int idx = tid; idx < 64 * OC; idx += 128) {
        int oc = idx % OC, ic = idx / OC;
        sW[idx] = wb[oc * 64 + ic];
    }
    const float* inb = in + (long)b * in_bstride + (long)ic_off * HW + pix0;
    for (int idx = tid; idx < 64 * PXT; idx += 128) {
        int px = idx % PXT, ic = idx / PXT;
        sIn[idx] = inb[(long)ic * HW + px];
    }
    __syncthreads();
    int og = tid % OCG, pg = tid / OCG;
    int oc0 = og * 8, p0 = pg * 4;
    float acc[8][4];
#pragma unroll
    for (int j = 0; j < 8; ++j)
#pragma unroll
        for (int p = 0; p < 4; ++p) acc[j][p] = 0.f;
#pragma unroll 4
    for (int ic = 0; ic < 64; ++ic) {
        float4 w0 = *(const float4*)&sW[ic * OC + oc0];
        float4 w1 = *(const float4*)&sW[ic * OC + oc0 + 4];
        float4 xv = *(const float4*)&sIn[ic * PXT + p0];
        float wv[8] = {w0.x, w0.y, w0.z, w0.w, w1.x, w1.y, w1.z, w1.w};
        float xa[4] = {xv.x, xv.y, xv.z, xv.w};
#pragma unroll
        for (int j = 0; j < 8; ++j)
#pragma unroll
            for (int p = 0; p < 4; ++p)
                acc[j][p] += wv[j] * xa[p];
    }
#pragma unroll
    for (int j = 0; j < 8; ++j) {
        long o = (long)(b * OC + oc0 + j) * HW + pix0 + p0;
        float4 r4 = make_float4(acc[j][0], acc[j][1], acc[j][2], acc[j][3]);
        if (RES) {
            float4 rr = *(const float4*)&res[o];
            r4.x += rr.x; r4.y += rr.y; r4.z += rr.z; r4.w += rr.w;
        }
        *(float4*)&out[o] = r4;
    }
}

// ---------------- depthwise 3x3, zero pad ----------------
__global__ void dw3x3_kernel(const float* __restrict__ in, const float* __restrict__ w,
                             float* __restrict__ out, int CH)
{
    int g = blockIdx.y;          // b*CH + c
    int c = g % CH;
    int p = blockIdx.x * 256 + threadIdx.x;
    int y = p >> 8, x = p & 255;
    const float* wp = w + c * 9;
    float wr[9];
#pragma unroll
    for (int t = 0; t < 9; ++t) wr[t] = wp[t];
    const float* ip = in + (long)g * HW;
    float acc = 0.f;
#pragma unroll
    for (int ky = 0; ky < 3; ++ky) {
        int iy = y + ky - 1;
        if (iy < 0 || iy > 255) continue;
#pragma unroll
        for (int kx = 0; kx < 3; ++kx) {
            int ix = x + kx - 1;
            if (ix < 0 || ix > 255) continue;
            acc += wr[ky * 3 + kx] * ip[iy * 256 + ix];
        }
    }
    out[(long)g * HW + p] = acc;
}

// ---------------- attention stats: per (b,head) gram G[16][16] + sumsq(q),sumsq(k) ----------------
// Two-stage deterministic reduction; stage 1 writes partials.
__global__ void attn_stats_kernel(const float* __restrict__ q, const float* __restrict__ k,
                                  float* __restrict__ part)
{
    __shared__ float sQ[16 * 129];
    __shared__ float sK[16 * 129];
    int g = blockIdx.y;
    int b = g >> 2, h = g & 3;
    const float* qb = q + (long)b * 64 * HW + (long)h * 16 * HW;
    const float* kb = k + (long)b * 128 * HW + (long)h * 16 * HW;
    int tid = threadIdx.x;
    int c = tid >> 4, d = tid & 15;
    float accG = 0.f, accQ = 0.f, accK = 0.f;
    int nbase = blockIdx.x * (HW / NCHUNK);
    for (int sub = 0; sub < (HW / NCHUNK) / 128; ++sub) {
        int n0 = nbase + sub * 128;
#pragma unroll
        for (int i = 0; i < 8; ++i) {
            int lin = tid + i * 256;
            int cc = lin >> 7, nn = lin & 127;
            sQ[cc * 129 + nn] = qb[(long)cc * HW + n0 + nn];
            sK[cc * 129 + nn] = kb[(long)cc * HW + n0 + nn];
        }
        __syncthreads();
        const float* qr = sQ + c * 129;
        const float* kr = sK + d * 129;
#pragma unroll 8
        for (int nn = 0; nn < 128; ++nn) accG += qr[nn] * kr[nn];
        if (d == 0) {
#pragma unroll 8
            for (int nn = 0; nn < 128; ++nn) accQ += qr[nn] * qr[nn];
        }
        if (c == 0) {
#pragma unroll 8
            for (int nn = 0; nn < 128; ++nn) accK += kr[nn] * kr[nn];
        }
        __syncthreads();
    }
    float* pp = part + ((long)g * NCHUNK + blockIdx.x) * 288;
    pp[tid] = accG;
    if (d == 0) pp[256 + c] = accQ;
    if (c == 0) pp[272 + d] = accK;
}

// ---------------- finish: reduce partials, normalize, softmax, fold with W_proj -> M[b][64][64] ----------------
__global__ void attn_finish_kernel(const float* __restrict__ part, const float* __restrict__ wproj,
                                   const float* __restrict__ temp, float* __restrict__ Mout)
{
    int b = blockIdx.x, tid = threadIdx.x;
    __shared__ float sG[4][256];
    __shared__ float sq[4][16], sk[4][16];
    __shared__ float sA[4][16][16];
    for (int h = 0; h < 4; ++h) {
        const float* pp = part + ((long)(b * 4 + h)) * NCHUNK * 288;
        float s = 0.f;
        for (int ch = 0; ch < NCHUNK; ++ch) s += pp[ch * 288 + tid];
        sG[h][tid] = s;
        if (tid < 32) {
            float s2 = 0.f;
            for (int ch = 0; ch < NCHUNK; ++ch) s2 += pp[ch * 288 + 256 + tid];
            if (tid < 16) sq[h][tid] = s2; else sk[h][tid - 16] = s2;
        }
    }
    __syncthreads();
    if (tid < 64) {
        int h = tid >> 4, c = tid & 15;
        float qn = fmaxf(sqrtf(sq[h][c]), 1e-12f);
        float tp = temp[h];
        float lg[16];
        float mx = -1e30f;
#pragma unroll
        for (int d = 0; d < 16; ++d) {
            float kn = fmaxf(sqrtf(sk[h][d]), 1e-12f);
            lg[d] = tp * sG[h][c * 16 + d] / (qn * kn);
            mx = fmaxf(mx, lg[d]);
        }
        float ssum = 0.f;
#pragma unroll
        for (int d = 0; d < 16; ++d) { lg[d] = expf(lg[d] - mx); ssum += lg[d]; }
        float inv = 1.f / ssum;
#pragma unroll
        for (int d = 0; d < 16; ++d) sA[h][c][d] = lg[d] * inv;
    }
    __syncthreads();
    // M[oc][j=h*16+d] = sum_r Wp[oc, h*16+r] * A[h][r][d]
    for (int e = tid; e < 4096; e += 256) {
        int oc = e >> 6, j = e & 63, h = j >> 4, d = j & 15;
        float s = 0.f;
#pragma unroll
        for (int r = 0; r < 16; ++r) s += wproj[oc * 64 + h * 16 + r] * sA[h][r][d];
        Mout[b * 4096 + e] = s;
    }
}

// ---------------- dense 3x3 conv 64->64, zero pad, optional gelu-on-input, optional residual ----------------
// Block tile: 32 oc x 8 rows x 32 cols. Thread: 1 oc x 4 rows x 8 cols. IC chunked by 8.
template<int ACT, bool RES>
__global__ void conv3x3_kernel(const float* __restrict__ in, const float* __restrict__ w,
                               const float* __restrict__ res, float* __restrict__ out)
{
    __shared__ float sIn[8 * 10 * 36];   // [ic_l][10 rows][36 pitch]
    __shared__ float sWs[8 * 9 * 32];    // [ic_l][tap][oc_l]
    int tid = threadIdx.x;
    int oc_l = tid >> 3;
    int rg = (tid >> 2) & 1;
    int cg = tid & 3;
    int bx = blockIdx.x & 7, by = blockIdx.x >> 3;
    int x0 = bx * 32, y0 = by * 8;
    int ocBase = blockIdx.y * 32;
    int b = blockIdx.z;
    float acc[4][8];
#pragma unroll
    for (int r = 0; r < 4; ++r)
#pragma unroll
        for (int cc = 0; cc < 8; ++cc) acc[r][cc] = 0.f;

    for (int icb = 0; icb < 8; ++icb) {
        int icBase = icb * 8;
        __syncthreads();
        // stage input 8ic x 10 x 34 (with halo, zero pad, optional gelu)
        for (int idx = tid; idx < 2720; idx += 256) {
            int ic_l = idx / 340;
            int rem = idx - ic_l * 340;
            int ry = rem / 34;
            int cx = rem - ry * 34;
            int gy = y0 - 1 + ry, gx = x0 - 1 + cx;
            float v = 0.f;
            if (gy >= 0 && gy < 256 && gx >= 0 && gx < 256) {
                v = in[(long)(b * 64 + icBase + ic_l) * HW + gy * 256 + gx];
                if (ACT == 1) v = gelu_f(v);
            }
            sIn[ic_l * 360 + ry * 36 + cx] = v;
        }
        // stage weights 8ic x 9 x 32oc
        for (int idx = tid; idx < 2304; idx += 256) {
            int oc = idx & 31;
            int t = (idx >> 5) % 9;
            int ic_l = idx / 288;
            sWs[idx] = w[((ocBase + oc) * 64 + icBase + ic_l) * 9 + t];
        }
        __syncthreads();
        for (int ic_l = 0; ic_l < 8; ++ic_l) {
            float wr[9];
#pragma unroll
            for (int t = 0; t < 9; ++t) wr[t] = sWs[(ic_l * 9 + t) * 32 + oc_l];
            const float* si = sIn + ic_l * 360 + cg * 8;
#pragma unroll
            for (int qq = 0; qq < 6; ++qq) {
                int riy = rg * 4 + qq;
                float v[10];
#pragma unroll
                for (int j = 0; j < 10; ++j) v[j] = si[riy * 36 + j];
#pragma unroll
                for (int ky = 0; ky < 3; ++ky) {
                    int r = qq - ky;
                    if (r >= 0 && r < 4) {
#pragma unroll
                        for (int kx = 0; kx < 3; ++kx) {
                            float wv = wr[ky * 3 + kx];
#pragma unroll
                            for (int cc = 0; cc < 8; ++cc)
                                acc[r][cc] += wv * v[cc + kx];
                        }
                    }
                }
            }
        }
    }
    int ox = x0 + cg * 8;
#pragma unroll
    for (int r = 0; r < 4; ++r) {
        int oy = y0 + rg * 4 + r;
        long o = (long)(b * 64 + ocBase + oc_l) * HW + oy * 256 + ox;
        float4 a0 = make_float4(acc[r][0], acc[r][1], acc[r][2], acc[r][3]);
        float4 a1 = make_float4(acc[r][4], acc[r][5], acc[r][6], acc[r][7]);
        if (RES) {
            float4 r0 = *(const float4*)&res[o];
            float4 r1 = *(const float4*)&res[o + 4];
            a0.x += r0.x; a0.y += r0.y; a0.z += r0.z; a0.w += r0.w;
            a1.x += r1.x; a1.y += r1.y; a1.z += r1.z; a1.w += r1.w;
        }
        *(float4*)&out[o] = a0;
        *(float4*)&out[o + 4] = a1;
    }
}

// ---------------- z = y * sigmoid(m2) + xadd ----------------
__global__ void mix_kernel(const float* __restrict__ y, const float* __restrict__ m2,
                           const float* __restrict__ xadd, float* __restrict__ z)
{
    int i = blockIdx.x * 256 + threadIdx.x;
    float m = m2[i];
    float s = 1.f / (1.f + expf(-m));
    z[i] = y[i] * s + xadd[i];
}

extern "C" void kernel_launch(void* const* d_in, const int* in_sizes, int n_in,
                              void* d_out, int out_size)
{
    const float* x       = (const float*)d_in[0];
    const float* ref     = (const float*)d_in[1];
    const float* ln1w    = (const float*)d_in[2];
    const float* ln1b    = (const float*)d_in[3];
    const float* ln2w    = (const float*)d_in[4];
    const float* ln2b    = (const float*)d_in[5];
    const float* ln3w    = (const float*)d_in[6];
    const float* ln3b    = (const float*)d_in[7];
    const float* w_kv    = (const float*)d_in[8];
    const float* w_kv_dw = (const float*)d_in[9];
    const float* w_q     = (const float*)d_in[10];
    const float* w_q_dw  = (const float*)d_in[11];
    const float* w_proj  = (const float*)d_in[12];
    const float* temp    = (const float*)d_in[13];
    const float* w_add1  = (const float*)d_in[14];
    const float* w_add2  = (const float*)d_in[15];
    const float* w_mul1  = (const float*)d_in[16];
    const float* w_fuse  = (const float*)d_in[17];
    float* out = (float*)d_out;

    float* pool = nullptr;
    cudaGetSymbolAddress((void**)&pool, g_pool);
    const long SZ = 16777216L, SZ2 = 33554432L;
    float* kv0  = pool;             // [B,128,HW] pre-dw
    float* kv1  = pool + SZ2;       // [B,128,HW] post-dw: k = ch 0..63, v = ch 64..127
    float* bufA = pool + 2 * SZ2;   // SZ
    float* bufB = bufA + SZ;
    float* bufC = bufB + SZ;
    float* bufD = bufC + SZ;
    float* bufE = bufD + SZ;
    float* x1   = bufE + SZ;
    float* Mb   = x1 + SZ;          // [B,64,64]
    float* part = Mb + 16384;       // stats partials

    // ---- Attention branch ----
    ln_kernel<<<1024, 256>>>(ref, ln1w, ln1b, bufA);                       // ln1(ref)
    ln_kernel<<<1024, 256>>>(x,   ln3w, ln3b, bufB);                       // ln3(x)
    conv1x1_kernel<128, false, false><<<dim3(2048, 4), 128>>>(bufA, w_kv, nullptr, kv0, 64 * HW, 0);
    conv1x1_kernel<64,  false, false><<<dim3(1024, 4), 128>>>(bufB, w_q,  nullptr, bufC, 64 * HW, 0);
    dw3x3_kernel<<<dim3(256, 512), 256>>>(kv0,  w_kv_dw, kv1,  128);
    dw3x3_kernel<<<dim3(256, 256), 256>>>(bufC, w_q_dw,  bufD, 64);
    attn_stats_kernel<<<dim3(NCHUNK, 16), 256>>>(bufD, kv1, part);
    attn_finish_kernel<<<4, 256>>>(part, w_proj, temp, Mb);
    // x1 = x + M_b @ v  (per-batch 1x1 conv over v, residual add)
    conv1x1_kernel<64, true, true><<<dim3(1024, 4), 128>>>(kv1, Mb, x, x1, 128 * HW, 64);

    // ---- SFM branch ----
    ln_kernel<<<1024, 256>>>(x1, ln2w, ln2b, bufA);                        // y = ln2(x1)
    conv3x3_kernel<0, false><<<dim3(256, 2, 4), 256>>>(bufA, w_add1, nullptr, bufB); // a1
    conv3x3_kernel<1, false><<<dim3(256, 2, 4), 256>>>(bufB, w_add2, nullptr, bufC); // x_add = conv(gelu(a1))
    conv3x3_kernel<0, false><<<dim3(256, 2, 4), 256>>>(bufA, w_mul1, nullptr, bufD); // m1
    conv3x3_kernel<1, false><<<dim3(256, 2, 4), 256>>>(bufD, w_mul1, nullptr, bufE); // m2 = conv(gelu(m1))
    mix_kernel<<<65536, 256>>>(bufA, bufE, bufC, bufB);                    // z = y*sigmoid(m2)+x_add
    conv3x3_kernel<0, true><<<dim3(256, 2, 4), 256>>>(bufB, w_fuse, x1, out); // out = x1 + conv(z)
}

// round 2
// speedup vs baseline: 1.0680x; 1.0680x over previous
#include <cuda_runtime.h>
#include <math.h>

typedef unsigned long long ull;
#define HW 65536
#define NCHUNK 64

__device__ float g_pool[168083456];

__device__ __forceinline__ float gelu_f(float v) {
    return 0.5f * v * (1.0f + erff(v * 0.70710678118654752f));
}
__device__ __forceinline__ ull pack2(float lo, float hi) {
    ull d; asm("mov.b64 %0,{%1,%2};" : "=l"(d) : "f"(lo), "f"(hi)); return d;
}
__device__ __forceinline__ void unpack2(ull v, float& lo, float& hi) {
    asm("mov.b64 {%0,%1},%2;" : "=f"(lo), "=f"(hi) : "l"(v));
}
__device__ __forceinline__ ull ffma2(ull a, ull b, ull c) {
    ull d; asm("fma.rn.f32x2 %0,%1,%2,%3;" : "=l"(d) : "l"(a), "l"(b), "l"(c)); return d;
}

// ---------------- LayerNorm over channel dim (per pixel) ----------------
__global__ void ln_kernel(const float* __restrict__ in, const float* __restrict__ w,
                          const float* __restrict__ bb, float* __restrict__ out)
{
    int p = blockIdx.x * blockDim.x + threadIdx.x;
    int b = p >> 16;
    int pix = p & 65535;
    const float* ip = in + (long)b * (64 * HW) + pix;
    float s = 0.f, ss = 0.f;
#pragma unroll 8
    for (int c = 0; c < 64; ++c) {
        float v = ip[(long)c * HW];
        s += v; ss += v * v;
    }
    float mu = s * (1.0f / 64);
    float var = ss * (1.0f / 64) - mu * mu;
    float r = rsqrtf(var + 1e-5f);
    float* op = out + (long)b * (64 * HW) + pix;
#pragma unroll 8
    for (int c = 0; c < 64; ++c) {
        float v = ip[(long)c * HW];
        op[(long)c * HW] = (v - mu) * r * w[c] + bb[c];
    }
}

// ---------------- 1x1 conv (optionally with fused channel-LN on input) ----------------
// 128 threads. Per thread: 8 oc x 8 px register tile, packed f32x2 math.
template<int OC, bool LNORM, bool PBW, bool RES>
__global__ void conv1x1_kernel(const float* __restrict__ in, const float* __restrict__ w,
                               const float* __restrict__ lnw, const float* __restrict__ lnb,
                               const float* __restrict__ res, float* __restrict__ out,
                               int in_bstride, int ic_off)
{
    constexpr int OCG = OC / 8;          // oc groups
    constexpr int PG  = 128 / OCG;       // pixel groups
    constexpr int PXT = PG * 8;          // pixel tile
    __shared__ float sW[64 * OC];        // [ic][oc]
    __shared__ float sIn[64 * PXT];      // [ic][px]
    int b = blockIdx.y;
    int pix0 = blockIdx.x * PXT;
    int tid = threadIdx.x;
    const float* wb = PBW ? (w + b * 64 * OC) : w;
    for (int idx = tid; idx < 64 * OC; idx += 128) {
        int oc = idx % OC, ic = idx / OC;
        sW[idx] = wb[oc * 64 + ic];
    }
    const float* inb = in + (long)b * in_bstride + (long)ic_off * HW + pix0;
    for (int idx = tid; idx < 64 * PXT; idx += 128) {
        int px = idx % PXT, ic = idx / PXT;
        sIn[idx] = inb[(long)ic * HW + px];
    }
    __syncthreads();
    if (LNORM) {
        if (tid < PXT) {
            float s = 0.f, ss = 0.f;
#pragma unroll 8
            for (int c = 0; c < 64; ++c) {
                float v = sIn[c * PXT + tid];
                s += v; ss += v * v;
            }
            float mu = s * (1.0f / 64);
            float var = ss * (1.0f / 64) - mu * mu;
            float r = rsqrtf(var + 1e-5f);
#pragma unroll 8
            for (int c = 0; c < 64; ++c) {
                sIn[c * PXT + tid] = (sIn[c * PXT + tid] - mu) * r * lnw[c] + lnb[c];
            }
        }
        __syncthreads();
    }
    int og = tid % OCG, pg = tid / OCG;
    int oc0 = og * 8, px0 = pg * 8;
    ull acc[8][4];
#pragma unroll
    for (int j = 0; j < 8; ++j)
#pragma unroll
        for (int k = 0; k < 4; ++k) acc[j][k] = 0ull;
#pragma unroll 2
    for (int ic = 0; ic < 64; ++ic) {
        const float4* wv4 = (const float4*)&sW[ic * OC + oc0];
        float4 wa = wv4[0], wbb = wv4[1];
        ull wp[8];
        wp[0] = pack2(wa.x, wa.x); wp[1] = pack2(wa.y, wa.y);
        wp[2] = pack2(wa.z, wa.z); wp[3] = pack2(wa.w, wa.w);
        wp[4] = pack2(wbb.x, wbb.x); wp[5] = pack2(wbb.y, wbb.y);
        wp[6] = pack2(wbb.z, wbb.z); wp[7] = pack2(wbb.w, wbb.w);
        const ull* xv = (const ull*)&sIn[ic * PXT + px0];
        ull x0 = xv[0], x1 = xv[1], x2 = xv[2], x3 = xv[3];
#pragma unroll
        for (int j = 0; j < 8; ++j) {
            acc[j][0] = ffma2(wp[j], x0, acc[j][0]);
            acc[j][1] = ffma2(wp[j], x1, acc[j][1]);
            acc[j][2] = ffma2(wp[j], x2, acc[j][2]);
            acc[j][3] = ffma2(wp[j], x3, acc[j][3]);
        }
    }
#pragma unroll
    for (int j = 0; j < 8; ++j) {
        long o = (long)(b * OC + oc0 + j) * HW + pix0 + px0;
        float v[8];
#pragma unroll
        for (int k = 0; k < 4; ++k) unpack2(acc[j][k], v[2 * k], v[2 * k + 1]);
        float4 a0 = make_float4(v[0], v[1], v[2], v[3]);
        float4 a1 = make_float4(v[4], v[5], v[6], v[7]);
        if (RES) {
            float4 r0 = *(const float4*)&res[o];
            float4 r1 = *(const float4*)&res[o + 4];
            a0.x += r0.x; a0.y += r0.y; a0.z += r0.z; a0.w += r0.w;
            a1.x += r1.x; a1.y += r1.y; a1.z += r1.z; a1.w += r1.w;
        }
        *(float4*)&out[o] = a0;
        *(float4*)&out[o + 4] = a1;
    }
}

// ---------------- depthwise 3x3, zero pad ----------------
__global__ void dw3x3_kernel(const float* __restrict__ in, const float* __restrict__ w,
                             float* __restrict__ out, int CH)
{
    int g = blockIdx.y;
    int c = g % CH;
    int p = blockIdx.x * 256 + threadIdx.x;
    int y = p >> 8, x = p & 255;
    const float* wp = w + c * 9;
    float wr[9];
#pragma unroll
    for (int t = 0; t < 9; ++t) wr[t] = wp[t];
    const float* ip = in + (long)g * HW;
    float acc = 0.f;
#pragma unroll
    for (int ky = 0; ky < 3; ++ky) {
        int iy = y + ky - 1;
        if (iy < 0 || iy > 255) continue;
#pragma unroll
        for (int kx = 0; kx < 3; ++kx) {
            int ix = x + kx - 1;
            if (ix < 0 || ix > 255) continue;
            acc += wr[ky * 3 + kx] * ip[iy * 256 + ix];
        }
    }
    out[(long)g * HW + p] = acc;
}

// ---------------- attention stats ----------------
__global__ void attn_stats_kernel(const float* __restrict__ q, const float* __restrict__ k,
                                  float* __restrict__ part)
{
    __shared__ float sQ[16 * 129];
    __shared__ float sK[16 * 129];
    int g = blockIdx.y;
    int b = g >> 2, h = g & 3;
    const float* qb = q + (long)b * 64 * HW + (long)h * 16 * HW;
    const float* kb = k + (long)b * 128 * HW + (long)h * 16 * HW;
    int tid = threadIdx.x;
    int c = tid >> 4, d = tid & 15;
    float accG = 0.f, accQ = 0.f, accK = 0.f;
    int nbase = blockIdx.x * (HW / NCHUNK);
    for (int sub = 0; sub < (HW / NCHUNK) / 128; ++sub) {
        int n0 = nbase + sub * 128;
#pragma unroll
        for (int i = 0; i < 8; ++i) {
            int lin = tid + i * 256;
            int cc = lin >> 7, nn = lin & 127;
            sQ[cc * 129 + nn] = qb[(long)cc * HW + n0 + nn];
            sK[cc * 129 + nn] = kb[(long)cc * HW + n0 + nn];
        }
        __syncthreads();
        const float* qr = sQ + c * 129;
        const float* kr = sK + d * 129;
#pragma unroll 8
        for (int nn = 0; nn < 128; ++nn) accG += qr[nn] * kr[nn];
        if (d == 0) {
#pragma unroll 8
            for (int nn = 0; nn < 128; ++nn) accQ += qr[nn] * qr[nn];
        }
        if (c == 0) {
#pragma unroll 8
            for (int nn = 0; nn < 128; ++nn) accK += kr[nn] * kr[nn];
        }
        __syncthreads();
    }
    float* pp = part + ((long)g * NCHUNK + blockIdx.x) * 288;
    pp[tid] = accG;
    if (d == 0) pp[256 + c] = accQ;
    if (c == 0) pp[272 + d] = accK;
}

// ---------------- finish: softmax + fold W_proj -> M[b][64][64] ----------------
__global__ void attn_finish_kernel(const float* __restrict__ part, const float* __restrict__ wproj,
                                   const float* __restrict__ temp, float* __restrict__ Mout)
{
    int b = blockIdx.x, tid = threadIdx.x;
    __shared__ float sG[4][256];
    __shared__ float sq[4][16], sk[4][16];
    __shared__ float sA[4][16][16];
    for (int h = 0; h < 4; ++h) {
        const float* pp = part + ((long)(b * 4 + h)) * NCHUNK * 288;
        float s = 0.f;
        for (int ch = 0; ch < NCHUNK; ++ch) s += pp[ch * 288 + tid];
        sG[h][tid] = s;
        if (tid < 32) {
            float s2 = 0.f;
            for (int ch = 0; ch < NCHUNK; ++ch) s2 += pp[ch * 288 + 256 + tid];
            if (tid < 16) sq[h][tid] = s2; else sk[h][tid - 16] = s2;
        }
    }
    __syncthreads();
    if (tid < 64) {
        int h = tid >> 4, c = tid & 15;
        float qn = fmaxf(sqrtf(sq[h][c]), 1e-12f);
        float tp = temp[h];
        float lg[16];
        float mx = -1e30f;
#pragma unroll
        for (int d = 0; d < 16; ++d) {
            float kn = fmaxf(sqrtf(sk[h][d]), 1e-12f);
            lg[d] = tp * sG[h][c * 16 + d] / (qn * kn);
            mx = fmaxf(mx, lg[d]);
        }
        float ssum = 0.f;
#pragma unroll
        for (int d = 0; d < 16; ++d) { lg[d] = expf(lg[d] - mx); ssum += lg[d]; }
        float inv = 1.f / ssum;
#pragma unroll
        for (int d = 0; d < 16; ++d) sA[h][c][d] = lg[d] * inv;
    }
    __syncthreads();
    for (int e = tid; e < 4096; e += 256) {
        int oc = e >> 6, j = e & 63, h = j >> 4, d = j & 15;
        float s = 0.f;
#pragma unroll
        for (int r = 0; r < 16; ++r) s += wproj[oc * 64 + h * 16 + r] * sA[h][r][d];
        Mout[b * 4096 + e] = s;
    }
}

// ---------------- dense 3x3 conv 64->64, packed f32x2 math ----------------
// EPI: 0 = none, 1 = gelu(out), 2 = mix: out = aux1*sigmoid(acc)+aux2, 3 = acc+aux1
template<int EPI>
__global__ void conv3x3_kernel(const float* __restrict__ in, const float* __restrict__ w,
                               const float* __restrict__ aux1, const float* __restrict__ aux2,
                               float* __restrict__ out)
{
    __shared__ float sIn[8 * 10 * 36];   // [ic_l][10 rows][36 pitch]
    __shared__ float sWs[8 * 9 * 32];    // [ic_l][tap][oc_l]
    int tid = threadIdx.x;
    int oc_l = tid >> 3;
    int rg = (tid >> 2) & 1;
    int cg = tid & 3;
    int bx = blockIdx.x & 7, by = blockIdx.x >> 3;
    int x0 = bx * 32, y0 = by * 8;
    int ocBase = blockIdx.y * 32;
    int b = blockIdx.z;
    ull acc[4][4];
#pragma unroll
    for (int r = 0; r < 4; ++r)
#pragma unroll
        for (int k = 0; k < 4; ++k) acc[r][k] = 0ull;

    for (int icb = 0; icb < 8; ++icb) {
        int icBase = icb * 8;
        __syncthreads();
        for (int idx = tid; idx < 2720; idx += 256) {
            int ic_l = idx / 340;
            int rem = idx - ic_l * 340;
            int ry = rem / 34;
            int cx = rem - ry * 34;
            int gy = y0 - 1 + ry, gx = x0 - 1 + cx;
            float v = 0.f;
            if (gy >= 0 && gy < 256 && gx >= 0 && gx < 256)
                v = in[(long)(b * 64 + icBase + ic_l) * HW + gy * 256 + gx];
            sIn[ic_l * 360 + ry * 36 + cx] = v;
        }
        for (int idx = tid; idx < 2304; idx += 256) {
            int oc = idx & 31;
            int t = (idx >> 5) % 9;
            int ic_l = idx / 288;
            sWs[idx] = w[((ocBase + oc) * 64 + icBase + ic_l) * 9 + t];
        }
        __syncthreads();
        for (int ic_l = 0; ic_l < 8; ++ic_l) {
            ull wp[9];
#pragma unroll
            for (int t = 0; t < 9; ++t) {
                float wv = sWs[(ic_l * 9 + t) * 32 + oc_l];
                wp[t] = pack2(wv, wv);
            }
            const float* si = sIn + ic_l * 360 + cg * 8;
#pragma unroll
            for (int qq = 0; qq < 6; ++qq) {
                const float* row = si + (rg * 4 + qq) * 36;
                float4 fa = *(const float4*)row;
                float4 fb = *(const float4*)(row + 4);
                float2 fc = *(const float2*)(row + 8);
                ull p0 = pack2(fa.x, fa.y), p1 = pack2(fa.z, fa.w);
                ull p2 = pack2(fb.x, fb.y), p3 = pack2(fb.z, fb.w);
                ull p4 = pack2(fc.x, fc.y);
                ull q0 = pack2(fa.y, fa.z), q1 = pack2(fa.w, fb.x);
                ull q2 = pack2(fb.y, fb.z), q3 = pack2(fb.w, fc.x);
#pragma unroll
                for (int ky = 0; ky < 3; ++ky) {
                    int r = qq - ky;
                    if (r >= 0 && r < 4) {
                        ull w0 = wp[ky * 3], w1 = wp[ky * 3 + 1], w2 = wp[ky * 3 + 2];
                        acc[r][0] = ffma2(w0, p0, acc[r][0]);
                        acc[r][0] = ffma2(w1, q0, acc[r][0]);
                        acc[r][0] = ffma2(w2, p1, acc[r][0]);
                        acc[r][1] = ffma2(w0, p1, acc[r][1]);
                        acc[r][1] = ffma2(w1, q1, acc[r][1]);
                        acc[r][1] = ffma2(w2, p2, acc[r][1]);
                        acc[r][2] = ffma2(w0, p2, acc[r][2]);
                        acc[r][2] = ffma2(w1, q2, acc[r][2]);
                        acc[r][2] = ffma2(w2, p3, acc[r][2]);
                        acc[r][3] = ffma2(w0, p3, acc[r][3]);
                        acc[r][3] = ffma2(w1, q3, acc[r][3]);
                        acc[r][3] = ffma2(w2, p4, acc[r][3]);
                    }
                }
            }
        }
    }
    int ox = x0 + cg * 8;
#pragma unroll
    for (int r = 0; r < 4; ++r) {
        int oy = y0 + rg * 4 + r;
        long o = (long)(b * 64 + ocBase + oc_l) * HW + oy * 256 + ox;
        float v[8];
#pragma unroll
        for (int k = 0; k < 4; ++k) unpack2(acc[r][k], v[2 * k], v[2 * k + 1]);
        if (EPI == 1) {
#pragma unroll
            for (int k = 0; k < 8; ++k) v[k] = gelu_f(v[k]);
        } else if (EPI == 2) {
            float4 y0v = *(const float4*)&aux1[o];
            float4 y1v = *(const float4*)&aux1[o + 4];
            float4 a0v = *(const float4*)&aux2[o];
            float4 a1v = *(const float4*)&aux2[o + 4];
            float ya[8] = {y0v.x, y0v.y, y0v.z, y0v.w, y1v.x, y1v.y, y1v.z, y1v.w};
            float aa[8] = {a0v.x, a0v.y, a0v.z, a0v.w, a1v.x, a1v.y, a1v.z, a1v.w};
#pragma unroll
            for (int k = 0; k < 8; ++k) {
                float s = 1.f / (1.f + expf(-v[k]));
                v[k] = ya[k] * s + aa[k];
            }
        } else if (EPI == 3) {
            float4 r0 = *(const float4*)&aux1[o];
            float4 r1 = *(const float4*)&aux1[o + 4];
            v[0] += r0.x; v[1] += r0.y; v[2] += r0.z; v[3] += r0.w;
            v[4] += r1.x; v[5] += r1.y; v[6] += r1.z; v[7] += r1.w;
        }
        *(float4*)&out[o] = make_float4(v[0], v[1], v[2], v[3]);
        *(float4*)&out[o + 4] = make_float4(v[4], v[5], v[6], v[7]);
    }
}

extern "C" void kernel_launch(void* const* d_in, const int* in_sizes, int n_in,
                              void* d_out, int out_size)
{
    const float* x       = (const float*)d_in[0];
    const float* ref     = (const float*)d_in[1];
    const float* ln1w    = (const float*)d_in[2];
    const float* ln1b    = (const float*)d_in[3];
    const float* ln2w    = (const float*)d_in[4];
    const float* ln2b    = (const float*)d_in[5];
    const float* ln3w    = (const float*)d_in[6];
    const float* ln3b    = (const float*)d_in[7];
    const float* w_kv    = (const float*)d_in[8];
    const float* w_kv_dw = (const float*)d_in[9];
    const float* w_q     = (const float*)d_in[10];
    const float* w_q_dw  = (const float*)d_in[11];
    const float* w_proj  = (const float*)d_in[12];
    const float* temp    = (const float*)d_in[13];
    const float* w_add1  = (const float*)d_in[14];
    const float* w_add2  = (const float*)d_in[15];
    const float* w_mul1  = (const float*)d_in[16];
    const float* w_fuse  = (const float*)d_in[17];
    float* out = (float*)d_out;

    float* pool = nullptr;
    cudaGetSymbolAddress((void**)&pool, g_pool);
    const long SZ = 16777216L, SZ2 = 33554432L;
    float* kv0  = pool;             // [B,128,HW] pre-dw
    float* kv1  = pool + SZ2;       // [B,128,HW] post-dw: k = ch 0..63, v = 64..127
    float* bufA = pool + 2 * SZ2;   // y = ln2(x1)
    float* bufB = bufA + SZ;        // ga1, then z
    float* bufC = bufB + SZ;        // q0, then x_add
    float* bufD = bufC + SZ;        // q1, then gm1
    float* bufE = bufD + SZ;        // z target
    float* x1   = bufE + SZ;
    float* Mb   = x1 + SZ;          // [B,64,64]
    float* part = Mb + 16384;

    // ---- Attention branch (LN fused into 1x1 convs) ----
    conv1x1_kernel<128, true, false, false><<<dim3(1024, 4), 128>>>(ref, w_kv, ln1w, ln1b, nullptr, kv0, 64 * HW, 0);
    conv1x1_kernel<64,  true, false, false><<<dim3(512, 4), 128>>>(x, w_q, ln3w, ln3b, nullptr, bufC, 64 * HW, 0);
    dw3x3_kernel<<<dim3(256, 512), 256>>>(kv0,  w_kv_dw, kv1,  128);
    dw3x3_kernel<<<dim3(256, 256), 256>>>(bufC, w_q_dw,  bufD, 64);
    attn_stats_kernel<<<dim3(NCHUNK, 16), 256>>>(bufD, kv1, part);
    attn_finish_kernel<<<4, 256>>>(part, w_proj, temp, Mb);
    // x1 = x + M_b @ v
    conv1x1_kernel<64, false, true, true><<<dim3(512, 4), 128>>>(kv1, Mb, nullptr, nullptr, x, x1, 128 * HW, 64);

    // ---- SFM branch ----
    ln_kernel<<<1024, 256>>>(x1, ln2w, ln2b, bufA);                                     // y
    conv3x3_kernel<1><<<dim3(256, 2, 4), 256>>>(bufA, w_add1, nullptr, nullptr, bufB);  // ga1 = gelu(conv)
    conv3x3_kernel<0><<<dim3(256, 2, 4), 256>>>(bufB, w_add2, nullptr, nullptr, bufC);  // x_add
    conv3x3_kernel<1><<<dim3(256, 2, 4), 256>>>(bufA, w_mul1, nullptr, nullptr, bufD);  // gm1 = gelu(conv)
    conv3x3_kernel<2><<<dim3(256, 2, 4), 256>>>(bufD, w_mul1, bufA, bufC, bufE);        // z = y*sig(conv)+x_add
    conv3x3_kernel<3><<<dim3(256, 2, 4), 256>>>(bufE, w_fuse, x1, nullptr, out);        // out = x1 + conv(z)
}

// round 3
// speedup vs baseline: 2.7689x; 2.5925x over previous
#include <cuda_runtime.h>
#include <math.h>

typedef unsigned long long ull;
#define HW 65536
#define NCHUNK 64

// pool: 2*SZ2 + 6*SZ + 16384 + 294912 + 147456
__device__ float g_pool[168230912];

__device__ __forceinline__ float gelu_f(float v) {
    return 0.5f * v * (1.0f + erff(v * 0.70710678118654752f));
}
__device__ __forceinline__ ull pack2(float lo, float hi) {
    ull d; asm("mov.b64 %0,{%1,%2};" : "=l"(d) : "f"(lo), "f"(hi)); return d;
}
__device__ __forceinline__ void unpack2(ull v, float& lo, float& hi) {
    asm("mov.b64 {%0,%1},%2;" : "=f"(lo), "=f"(hi) : "l"(v));
}
__device__ __forceinline__ ull ffma2(ull a, ull b, ull c) {
    ull d; asm("fma.rn.f32x2 %0,%1,%2,%3;" : "=l"(d) : "l"(a), "l"(b), "l"(c)); return d;
}
__device__ __forceinline__ unsigned smaddr(const void* p) {
    unsigned a;
    asm("{.reg .u64 t; cvta.to.shared.u64 t, %1; cvt.u32.u64 %0, t;}" : "=r"(a) : "l"(p));
    return a;
}
__device__ __forceinline__ void cpa4(unsigned s, const void* g, bool pred) {
    int sz = pred ? 4 : 0;
    asm volatile("cp.async.ca.shared.global [%0], [%1], 4, %2;" :: "r"(s), "l"(g), "r"(sz));
}
__device__ __forceinline__ void cpa16(unsigned s, const void* g) {
    asm volatile("cp.async.cg.shared.global [%0], [%1], 16;" :: "r"(s), "l"(g));
}
__device__ __forceinline__ void cpa_commit() { asm volatile("cp.async.commit_group;"); }
__device__ __forceinline__ void cpa_wait1() { asm volatile("cp.async.wait_group 1;"); }
__device__ __forceinline__ void cpa_wait0() { asm volatile("cp.async.wait_group 0;"); }

// ---------------- weight transpose: [oc][ic][9] -> [(ic*9+t)*64+oc] ----------------
__global__ void wtrans_kernel(const float* __restrict__ w, float* __restrict__ wT)
{
    int o = blockIdx.x * 256 + threadIdx.x;   // 0..36863
    int oc = o & 63;
    int s = o >> 6;
    int t = s % 9;
    int ic = s / 9;
    wT[o] = w[(oc * 64 + ic) * 9 + t];
}

// ---------------- LayerNorm over channel dim (per pixel) ----------------
__global__ void ln_kernel(const float* __restrict__ in, const float* __restrict__ w,
                          const float* __restrict__ bb, float* __restrict__ out)
{
    int p = blockIdx.x * blockDim.x + threadIdx.x;
    int b = p >> 16;
    int pix = p & 65535;
    const float* ip = in + (long)b * (64 * HW) + pix;
    float s = 0.f, ss = 0.f;
#pragma unroll 8
    for (int c = 0; c < 64; ++c) {
        float v = ip[(long)c * HW];
        s += v; ss += v * v;
    }
    float mu = s * (1.0f / 64);
    float var = ss * (1.0f / 64) - mu * mu;
    float r = rsqrtf(var + 1e-5f);
    float* op = out + (long)b * (64 * HW) + pix;
#pragma unroll 8
    for (int c = 0; c < 64; ++c) {
        float v = ip[(long)c * HW];
        op[(long)c * HW] = (v - mu) * r * w[c] + bb[c];
    }
}

// ---------------- 1x1 conv (optionally with fused channel-LN on input) ----------------
template<int OC, bool LNORM, bool PBW, bool RES>
__global__ void conv1x1_kernel(const float* __restrict__ in, const float* __restrict__ w,
                               const float* __restrict__ lnw, const float* __restrict__ lnb,
                               const float* __restrict__ res, float* __restrict__ out,
                               int in_bstride, int ic_off)
{
    constexpr int OCG = OC / 8;
    constexpr int PG  = 128 / OCG;
    constexpr int PXT = PG * 8;
    __shared__ float sW[64 * OC];
    __shared__ float sIn[64 * PXT];
    int b = blockIdx.y;
    int pix0 = blockIdx.x * PXT;
    int tid = threadIdx.x;
    const float* wb = PBW ? (w + b * 64 * OC) : w;
    for (int idx = tid; idx < 64 * OC; idx += 128) {
        int oc = idx % OC, ic = idx / OC;
        sW[idx] = wb[oc * 64 + ic];
    }
    const float* inb = in + (long)b * in_bstride + (long)ic_off * HW + pix0;
    for (int idx = tid; idx < 64 * PXT; idx += 128) {
        int px = idx % PXT, ic = idx / PXT;
        sIn[idx] = inb[(long)ic * HW + px];
    }
    __syncthreads();
    if (LNORM) {
        if (tid < PXT) {
            float s = 0.f, ss = 0.f;
#pragma unroll 8
            for (int c = 0; c < 64; ++c) {
                float v = sIn[c * PXT + tid];
                s += v; ss += v * v;
            }
            float mu = s * (1.0f / 64);
            float var = ss * (1.0f / 64) - mu * mu;
            float r = rsqrtf(var + 1e-5f);
#pragma unroll 8
            for (int c = 0; c < 64; ++c) {
                sIn[c * PXT + tid] = (sIn[c * PXT + tid] - mu) * r * lnw[c] + lnb[c];
            }
        }
        __syncthreads();
    }
    int og = tid % OCG, pg = tid / OCG;
    int oc0 = og * 8, px0 = pg * 8;
    ull acc[8][4];
#pragma unroll
    for (int j = 0; j < 8; ++j)
#pragma unroll
        for (int k = 0; k < 4; ++k) acc[j][k] = 0ull;
#pragma unroll 2
    for (int ic = 0; ic < 64; ++ic) {
        const float4* wv4 = (const float4*)&sW[ic * OC + oc0];
        float4 wa = wv4[0], wbb = wv4[1];
        ull wp[8];
        wp[0] = pack2(wa.x, wa.x); wp[1] = pack2(wa.y, wa.y);
        wp[2] = pack2(wa.z, wa.z); wp[3] = pack2(wa.w, wa.w);
        wp[4] = pack2(wbb.x, wbb.x); wp[5] = pack2(wbb.y, wbb.y);
        wp[6] = pack2(wbb.z, wbb.z); wp[7] = pack2(wbb.w, wbb.w);
        const ull* xv = (const ull*)&sIn[ic * PXT + px0];
        ull x0 = xv[0], x1 = xv[1], x2 = xv[2], x3 = xv[3];
#pragma unroll
        for (int j = 0; j < 8; ++j) {
            acc[j][0] = ffma2(wp[j], x0, acc[j][0]);
            acc[j][1] = ffma2(wp[j], x1, acc[j][1]);
            acc[j][2] = ffma2(wp[j], x2, acc[j][2]);
            acc[j][3] = ffma2(wp[j], x3, acc[j][3]);
        }
    }
#pragma unroll
    for (int j = 0; j < 8; ++j) {
        long o = (long)(b * OC + oc0 + j) * HW + pix0 + px0;
        float v[8];
#pragma unroll
        for (int k = 0; k < 4; ++k) unpack2(acc[j][k], v[2 * k], v[2 * k + 1]);
        float4 a0 = make_float4(v[0], v[1], v[2], v[3]);
        float4 a1 = make_float4(v[4], v[5], v[6], v[7]);
        if (RES) {
            float4 r0 = *(const float4*)&res[o];
            float4 r1 = *(const float4*)&res[o + 4];
            a0.x += r0.x; a0.y += r0.y; a0.z += r0.z; a0.w += r0.w;
            a1.x += r1.x; a1.y += r1.y; a1.z += r1.z; a1.w += r1.w;
        }
        *(float4*)&out[o] = a0;
        *(float4*)&out[o + 4] = a1;
    }
}

// ---------------- depthwise 3x3 v2: 8 px per thread, vector fast path ----------------
template<int CH>
__global__ void dw3x3_kernel(const float* __restrict__ in, const float* __restrict__ w,
                             float* __restrict__ out)
{
    int p = blockIdx.x * 256 + threadIdx.x;
    int xg = p & 31;
    int y = (p >> 5) & 255;
    int g = p >> 13;              // b*CH + c
    int c = g & (CH - 1);
    int x0 = xg * 8;
    const float* wp = w + c * 9;
    float wr[9];
#pragma unroll
    for (int t = 0; t < 9; ++t) wr[t] = wp[t];
    const float* ip = in + (long)g * HW;
    float r[3][10];
    bool interior = (y > 0) && (y < 255) && (xg > 0) && (xg < 31);
    if (interior) {
#pragma unroll
        for (int rr = 0; rr < 3; ++rr) {
            const float* base = ip + (y - 1 + rr) * 256 + x0;
            float4 a = *(const float4*)base;
            float4 bq = *(const float4*)(base + 4);
            r[rr][0] = base[-1];
            r[rr][1] = a.x; r[rr][2] = a.y; r[rr][3] = a.z; r[rr][4] = a.w;
            r[rr][5] = bq.x; r[rr][6] = bq.y; r[rr][7] = bq.z; r[rr][8] = bq.w;
            r[rr][9] = base[8];
        }
    } else {
#pragma unroll
        for (int rr = 0; rr < 3; ++rr) {
            int iy = y - 1 + rr;
#pragma unroll
            for (int j = 0; j < 10; ++j) {
                int ix = x0 - 1 + j;
                r[rr][j] = (iy >= 0 && iy < 256 && ix >= 0 && ix < 256) ? ip[iy * 256 + ix] : 0.f;
            }
        }
    }
    float acc[8];
#pragma unroll
    for (int q = 0; q < 8; ++q) acc[q] = 0.f;
#pragma unroll
    for (int ky = 0; ky < 3; ++ky)
#pragma unroll
        for (int kx = 0; kx < 3; ++kx) {
            float wv = wr[ky * 3 + kx];
#pragma unroll
            for (int q = 0; q < 8; ++q) acc[q] += wv * r[ky][q + kx];
        }
    float* op = out + (long)g * HW + y * 256 + x0;
    *(float4*)op = make_float4(acc[0], acc[1], acc[2], acc[3]);
    *(float4*)(op + 4) = make_float4(acc[4], acc[5], acc[6], acc[7]);
}

// ---------------- attention stats ----------------
__global__ void attn_stats_kernel(const float* __restrict__ q, const float* __restrict__ k,
                                  float* __restrict__ part)
{
    __shared__ float sQ[16 * 129];
    __shared__ float sK[16 * 129];
    int g = blockIdx.y;
    int b = g >> 2, h = g & 3;
    const float* qb = q + (long)b * 64 * HW + (long)h * 16 * HW;
    const float* kb = k + (long)b * 128 * HW + (long)h * 16 * HW;
    int tid = threadIdx.x;
    int c = tid >> 4, d = tid & 15;
    float accG = 0.f, accQ = 0.f, accK = 0.f;
    int nbase = blockIdx.x * (HW / NCHUNK);
    for (int sub = 0; sub < (HW / NCHUNK) / 128; ++sub) {
        int n0 = nbase + sub * 128;
#pragma unroll
        for (int i = 0; i < 8; ++i) {
            int lin = tid + i * 256;
            int cc = lin >> 7, nn = lin & 127;
            sQ[cc * 129 + nn] = qb[(long)cc * HW + n0 + nn];
            sK[cc * 129 + nn] = kb[(long)cc * HW + n0 + nn];
        }
        __syncthreads();
        const float* qr = sQ + c * 129;
        const float* kr = sK + d * 129;
#pragma unroll 8
        for (int nn = 0; nn < 128; ++nn) accG += qr[nn] * kr[nn];
        if (d == 0) {
#pragma unroll 8
            for (int nn = 0; nn < 128; ++nn) accQ += qr[nn] * qr[nn];
        }
        if (c == 0) {
#pragma unroll 8
            for (int nn = 0; nn < 128; ++nn) accK += kr[nn] * kr[nn];
        }
        __syncthreads();
    }
    float* pp = part + ((long)g * NCHUNK + blockIdx.x) * 288;
    pp[tid] = accG;
    if (d == 0) pp[256 + c] = accQ;
    if (c == 0) pp[272 + d] = accK;
}

// ---------------- finish: softmax + fold W_proj -> M[b][64][64] ----------------
__global__ void attn_finish_kernel(const float* __restrict__ part, const float* __restrict__ wproj,
                                   const float* __restrict__ temp, float* __restrict__ Mout)
{
    int b = blockIdx.x, tid = threadIdx.x;
    __shared__ float sG[4][256];
    __shared__ float sq[4][16], sk[4][16];
    __shared__ float sA[4][16][16];
    for (int h = 0; h < 4; ++h) {
        const float* pp = part + ((long)(b * 4 + h)) * NCHUNK * 288;
        float s = 0.f;
        for (int ch = 0; ch < NCHUNK; ++ch) s += pp[ch * 288 + tid];
        sG[h][tid] = s;
        if (tid < 32) {
            float s2 = 0.f;
            for (int ch = 0; ch < NCHUNK; ++ch) s2 += pp[ch * 288 + 256 + tid];
            if (tid < 16) sq[h][tid] = s2; else sk[h][tid - 16] = s2;
        }
    }
    __syncthreads();
    if (tid < 64) {
        int h = tid >> 4, c = tid & 15;
        float qn = fmaxf(sqrtf(sq[h][c]), 1e-12f);
        float tp = temp[h];
        float lg[16];
        float mx = -1e30f;
#pragma unroll
        for (int d = 0; d < 16; ++d) {
            float kn = fmaxf(sqrtf(sk[h][d]), 1e-12f);
            lg[d] = tp * sG[h][c * 16 + d] / (qn * kn);
            mx = fmaxf(mx, lg[d]);
        }
        float ssum = 0.f;
#pragma unroll
        for (int d = 0; d < 16; ++d) { lg[d] = expf(lg[d] - mx); ssum += lg[d]; }
        float inv = 1.f / ssum;
#pragma unroll
        for (int d = 0; d < 16; ++d) sA[h][c][d] = lg[d] * inv;
    }
    __syncthreads();
    for (int e = tid; e < 4096; e += 256) {
        int oc = e >> 6, j = e & 63, h = j >> 4, d = j & 15;
        float s = 0.f;
#pragma unroll
        for (int r = 0; r < 16; ++r) s += wproj[oc * 64 + h * 16 + r] * sA[h][r][d];
        Mout[b * 4096 + e] = s;
    }
}

// ---------------- dense 3x3 conv v2: oc-paired f32x2, cp.async double-buffered ----------------
// Block: 256 thr, output 64 oc x (4 rows x 64 cols). Thread: 8 oc x 8 px.
// Weights pre-transposed to [(ic*9+t)*64 + oc].
// EPI: 0 none, 1 gelu, 2 mix out=aux1*sigmoid(acc)+aux2, 3 acc+aux1
template<int EPI>
__global__ void __launch_bounds__(256, 2)
conv3x3_kernel(const float* __restrict__ in, const float* __restrict__ wT,
               const float* __restrict__ aux1, const float* __restrict__ aux2,
               float* __restrict__ out)
{
    __shared__ float sx[2][4][6][68];
    __shared__ float4 sw4[2][576];      // [ic_l][tap][oc] as float4

    int tid = threadIdx.x;
    int bx = blockIdx.x;
    int b = blockIdx.y;
    int tx = bx & 3, ty = bx >> 2;
    int x0 = tx * 64, y0 = ty * 4;
    int ocg = tid >> 5;
    int pxg = tid & 31;
    int row = pxg >> 3;
    int colg = pxg & 7;
    int oc0 = ocg * 8;

    const float* inb = in + (long)b * (64 * HW);

    // ---- staging lambda-ish (macro by hand) ----
    // input chunk icb covers ic = icb*4 .. +3
#define STAGE(ICB, BUF) do { \
        int icBase = (ICB) * 4; \
        for (int idx = tid; idx < 1632; idx += 256) { \
            int ic_l = idx / 408; \
            int rem = idx - ic_l * 408; \
            int ry = rem / 68; \
            int cx = rem - ry * 68; \
            int gy = y0 - 1 + ry; \
            int gx = x0 - 2 + cx; \
            bool ok = (gy >= 0) && (gy < 256) && (gx >= 0) && (gx < 256); \
            const float* gsrc = ok ? (inb + (long)(icBase + ic_l) * HW + gy * 256 + gx) : inb; \
            cpa4(smaddr(&sx[BUF][ic_l][ry][cx]), gsrc, ok); \
        } \
        const float4* wsrc = (const float4*)(wT + (long)icBase * 576); \
        for (int idx = tid; idx < 576; idx += 256) { \
            cpa16(smaddr(&sw4[BUF][idx]), wsrc + idx); \
        } \
    } while (0)

    ull acc[4][8];
#pragma unroll
    for (int j = 0; j < 4; ++j)
#pragma unroll
        for (int p2 = 0; p2 < 8; ++p2) acc[j][p2] = 0ull;

    STAGE(0, 0);
    cpa_commit();

    for (int icb = 0; icb < 16; ++icb) {
        int buf = icb & 1;
        if (icb < 15) {
            STAGE(icb + 1, (icb + 1) & 1);
            cpa_commit();
            cpa_wait1();
        } else {
            cpa_wait0();
        }
        __syncthreads();
        const float* swf = (const float*)sw4[buf];
#pragma unroll
        for (int ic_l = 0; ic_l < 4; ++ic_l) {
#pragma unroll
            for (int ky = 0; ky < 3; ++ky) {
                const float* xs = &sx[buf][ic_l][row + ky][colg * 8 + 1];
                ull xp[10];
#pragma unroll
                for (int j = 0; j < 10; ++j) {
                    float xv = xs[j];
                    xp[j] = pack2(xv, xv);
                }
#pragma unroll
                for (int kx = 0; kx < 3; ++kx) {
                    const ull* wp = (const ull*)&swf[(ic_l * 9 + ky * 3 + kx) * 64 + oc0];
                    ull w0 = wp[0], w1 = wp[1], w2 = wp[2], w3 = wp[3];
#pragma unroll
                    for (int p2 = 0; p2 < 8; ++p2) {
                        ull xv = xp[p2 + kx];
                        acc[0][p2] = ffma2(w0, xv, acc[0][p2]);
                        acc[1][p2] = ffma2(w1, xv, acc[1][p2]);
                        acc[2][p2] = ffma2(w2, xv, acc[2][p2]);
                        acc[3][p2] = ffma2(w3, xv, acc[3][p2]);
                    }
                }
            }
        }
        __syncthreads();
    }
#undef STAGE

    // ---- epilogue ----
    float v[8][8];
#pragma unroll
    for (int j = 0; j < 4; ++j)
#pragma unroll
        for (int p2 = 0; p2 < 8; ++p2)
            unpack2(acc[j][p2], v[2 * j][p2], v[2 * j + 1][p2]);

    long base = (long)(b * 64 + oc0) * HW + (y0 + row) * 256 + x0 + colg * 8;
#pragma unroll
    for (int ol = 0; ol < 8; ++ol) {
        long o = base + (long)ol * HW;
        float* vv = v[ol];
        if (EPI == 1) {
#pragma unroll
            for (int k = 0; k < 8; ++k) vv[k] = gelu_f(vv[k]);
        } else if (EPI == 2) {
            float4 y0v = *(const float4*)&aux1[o];
            float4 y1v = *(const float4*)&aux1[o + 4];
            float4 a0v = *(const float4*)&aux2[o];
            float4 a1v = *(const float4*)&aux2[o + 4];
            float ya[8] = {y0v.x, y0v.y, y0v.z, y0v.w, y1v.x, y1v.y, y1v.z, y1v.w};
            float aa[8] = {a0v.x, a0v.y, a0v.z, a0v.w, a1v.x, a1v.y, a1v.z, a1v.w};
#pragma unroll
            for (int k = 0; k < 8; ++k) {
                float s = 1.f / (1.f + expf(-vv[k]));
                vv[k] = ya[k] * s + aa[k];
            }
        } else if (EPI == 3) {
            float4 r0 = *(const float4*)&aux1[o];
            float4 r1 = *(const float4*)&aux1[o + 4];
            vv[0] += r0.x; vv[1] += r0.y; vv[2] += r0.z; vv[3] += r0.w;
            vv[4] += r1.x; vv[5] += r1.y; vv[6] += r1.z; vv[7] += r1.w;
        }
        *(float4*)&out[o] = make_float4(vv[0], vv[1], vv[2], vv[3]);
        *(float4*)&out[o + 4] = make_float4(vv[4], vv[5], vv[6], vv[7]);
    }
}

extern "C" void kernel_launch(void* const* d_in, const int* in_sizes, int n_in,
                              void* d_out, int out_size)
{
    const float* x       = (const float*)d_in[0];
    const float* ref     = (const float*)d_in[1];
    const float* ln1w    = (const float*)d_in[2];
    const float* ln1b    = (const float*)d_in[3];
    const float* ln2w    = (const float*)d_in[4];
    const float* ln2b    = (const float*)d_in[5];
    const float* ln3w    = (const float*)d_in[6];
    const float* ln3b    = (const float*)d_in[7];
    const float* w_kv    = (const float*)d_in[8];
    const float* w_kv_dw = (const float*)d_in[9];
    const float* w_q     = (const float*)d_in[10];
    const float* w_q_dw  = (const float*)d_in[11];
    const float* w_proj  = (const float*)d_in[12];
    const float* temp    = (const float*)d_in[13];
    const float* w_add1  = (const float*)d_in[14];
    const float* w_add2  = (const float*)d_in[15];
    const float* w_mul1  = (const float*)d_in[16];
    const float* w_fuse  = (const float*)d_in[17];
    float* out = (float*)d_out;

    float* pool = nullptr;
    cudaGetSymbolAddress((void**)&pool, g_pool);
    const long SZ = 16777216L, SZ2 = 33554432L;
    float* kv0  = pool;
    float* kv1  = pool + SZ2;
    float* bufA = pool + 2 * SZ2;
    float* bufB = bufA + SZ;
    float* bufC = bufB + SZ;
    float* bufD = bufC + SZ;
    float* bufE = bufD + SZ;
    float* x1   = bufE + SZ;
    float* Mb   = x1 + SZ;
    float* part = Mb + 16384;
    float* wTa1 = part + 294912;
    float* wTa2 = wTa1 + 36864;
    float* wTm  = wTa2 + 36864;
    float* wTf  = wTm + 36864;

    // weight transposes (tiny, run first)
    wtrans_kernel<<<144, 256>>>(w_add1, wTa1);
    wtrans_kernel<<<144, 256>>>(w_add2, wTa2);
    wtrans_kernel<<<144, 256>>>(w_mul1, wTm);
    wtrans_kernel<<<144, 256>>>(w_fuse, wTf);

    // ---- Attention branch ----
    conv1x1_kernel<128, true, false, false><<<dim3(1024, 4), 128>>>(ref, w_kv, ln1w, ln1b, nullptr, kv0, 64 * HW, 0);
    conv1x1_kernel<64,  true, false, false><<<dim3(512, 4), 128>>>(x, w_q, ln3w, ln3b, nullptr, bufC, 64 * HW, 0);
    dw3x3_kernel<128><<<16384, 256>>>(kv0,  w_kv_dw, kv1);
    dw3x3_kernel<64><<<8192, 256>>>(bufC, w_q_dw, bufD);
    attn_stats_kernel<<<dim3(NCHUNK, 16), 256>>>(bufD, kv1, part);
    attn_finish_kernel<<<4, 256>>>(part, w_proj, temp, Mb);
    conv1x1_kernel<64, false, true, true><<<dim3(512, 4), 128>>>(kv1, Mb, nullptr, nullptr, x, x1, 128 * HW, 64);

    // ---- SFM branch ----
    ln_kernel<<<1024, 256>>>(x1, ln2w, ln2b, bufA);                                     // y
    conv3x3_kernel<1><<<dim3(256, 4), 256>>>(bufA, wTa1, nullptr, nullptr, bufB);       // ga1
    conv3x3_kernel<0><<<dim3(256, 4), 256>>>(bufB, wTa2, nullptr, nullptr, bufC);       // x_add
    conv3x3_kernel<1><<<dim3(256, 4), 256>>>(bufA, wTm, nullptr, nullptr, bufD);        // gm1
    conv3x3_kernel<2><<<dim3(256, 4), 256>>>(bufD, wTm, bufA, bufC, bufE);              // z
    conv3x3_kernel<3><<<dim3(256, 4), 256>>>(bufE, wTf, x1, nullptr, out);              // out
}

// round 4
// speedup vs baseline: 2.7784x; 1.0034x over previous
#include <cuda_runtime.h>
#include <math.h>

typedef unsigned long long ull;
#define HW 65536
#define NCHUNK 64

// pool: 2*SZ2 + 6*SZ + 16384 + 294912 + 147456
__device__ float g_pool[168230912];

__device__ __forceinline__ float gelu_f(float v) {
    return 0.5f * v * (1.0f + erff(v * 0.70710678118654752f));
}
__device__ __forceinline__ ull pack2(float lo, float hi) {
    ull d; asm("mov.b64 %0,{%1,%2};" : "=l"(d) : "f"(lo), "f"(hi)); return d;
}
__device__ __forceinline__ void unpack2(ull v, float& lo, float& hi) {
    asm("mov.b64 {%0,%1},%2;" : "=f"(lo), "=f"(hi) : "l"(v));
}
__device__ __forceinline__ ull ffma2(ull a, ull b, ull c) {
    ull d; asm("fma.rn.f32x2 %0,%1,%2,%3;" : "=l"(d) : "l"(a), "l"(b), "l"(c)); return d;
}
__device__ __forceinline__ unsigned smaddr(const void* p) {
    unsigned a;
    asm("{.reg .u64 t; cvta.to.shared.u64 t, %1; cvt.u32.u64 %0, t;}" : "=r"(a) : "l"(p));
    return a;
}
__device__ __forceinline__ void cpa4(unsigned s, const void* g, bool pred) {
    int sz = pred ? 4 : 0;
    asm volatile("cp.async.ca.shared.global [%0], [%1], 4, %2;" :: "r"(s), "l"(g), "r"(sz));
}
__device__ __forceinline__ void cpa16(unsigned s, const void* g) {
    asm volatile("cp.async.cg.shared.global [%0], [%1], 16;" :: "r"(s), "l"(g));
}
__device__ __forceinline__ void cpa_commit() { asm volatile("cp.async.commit_group;"); }
__device__ __forceinline__ void cpa_wait1() { asm volatile("cp.async.wait_group 1;"); }
__device__ __forceinline__ void cpa_wait0() { asm volatile("cp.async.wait_group 0;"); }

// ---------------- weight transpose: [oc][ic][9] -> [(ic*9+t)*64+oc] ----------------
__global__ void wtrans_kernel(const float* __restrict__ w, float* __restrict__ wT)
{
    int o = blockIdx.x * 256 + threadIdx.x;   // 0..36863
    int oc = o & 63;
    int s = o >> 6;
    int t = s % 9;
    int ic = s / 9;
    wT[o] = w[(oc * 64 + ic) * 9 + t];
}

// ---------------- LayerNorm over channel dim (per pixel) ----------------
__global__ void ln_kernel(const float* __restrict__ in, const float* __restrict__ w,
                          const float* __restrict__ bb, float* __restrict__ out)
{
    int p = blockIdx.x * blockDim.x + threadIdx.x;
    int b = p >> 16;
    int pix = p & 65535;
    const float* ip = in + (long)b * (64 * HW) + pix;
    float s = 0.f, ss = 0.f;
#pragma unroll 8
    for (int c = 0; c < 64; ++c) {
        float v = ip[(long)c * HW];
        s += v; ss += v * v;
    }
    float mu = s * (1.0f / 64);
    float var = ss * (1.0f / 64) - mu * mu;
    float r = rsqrtf(var + 1e-5f);
    float* op = out + (long)b * (64 * HW) + pix;
#pragma unroll 8
    for (int c = 0; c < 64; ++c) {
        float v = ip[(long)c * HW];
        op[(long)c * HW] = (v - mu) * r * w[c] + bb[c];
    }
}

// ---------------- 1x1 conv (optionally with fused channel-LN on input) ----------------
template<int OC, bool LNORM, bool PBW, bool RES>
__global__ void conv1x1_kernel(const float* __restrict__ in, const float* __restrict__ w,
                               const float* __restrict__ lnw, const float* __restrict__ lnb,
                               const float* __restrict__ res, float* __restrict__ out,
                               int in_bstride, int ic_off)
{
    constexpr int OCG = OC / 8;
    constexpr int PG  = 128 / OCG;
    constexpr int PXT = PG * 8;
    __shared__ float sW[64 * OC];
    __shared__ float sIn[64 * PXT];
    int b = blockIdx.y;
    int pix0 = blockIdx.x * PXT;
    int tid = threadIdx.x;
    const float* wb = PBW ? (w + b * 64 * OC) : w;
    for (int idx = tid; idx < 64 * OC; idx += 128) {
        int oc = idx % OC, ic = idx / OC;
        sW[idx] = wb[oc * 64 + ic];
    }
    const float* inb = in + (long)b * in_bstride + (long)ic_off * HW + pix0;
    for (int idx = tid; idx < 64 * PXT; idx += 128) {
        int px = idx % PXT, ic = idx / PXT;
        sIn[idx] = inb[(long)ic * HW + px];
    }
    __syncthreads();
    if (LNORM) {
        if (tid < PXT) {
            float s = 0.f, ss = 0.f;
#pragma unroll 8
            for (int c = 0; c < 64; ++c) {
                float v = sIn[c * PXT + tid];
                s += v; ss += v * v;
            }
            float mu = s * (1.0f / 64);
            float var = ss * (1.0f / 64) - mu * mu;
            float r = rsqrtf(var + 1e-5f);
#pragma unroll 8
            for (int c = 0; c < 64; ++c) {
                sIn[c * PXT + tid] = (sIn[c * PXT + tid] - mu) * r * lnw[c] + lnb[c];
            }
        }
        __syncthreads();
    }
    int og = tid % OCG, pg = tid / OCG;
    int oc0 = og * 8, px0 = pg * 8;
    ull acc[8][4];
#pragma unroll
    for (int j = 0; j < 8; ++j)
#pragma unroll
        for (int k = 0; k < 4; ++k) acc[j][k] = 0ull;
#pragma unroll 2
    for (int ic = 0; ic < 64; ++ic) {
        const float4* wv4 = (const float4*)&sW[ic * OC + oc0];
        float4 wa = wv4[0], wbb = wv4[1];
        ull wp[8];
        wp[0] = pack2(wa.x, wa.x); wp[1] = pack2(wa.y, wa.y);
        wp[2] = pack2(wa.z, wa.z); wp[3] = pack2(wa.w, wa.w);
        wp[4] = pack2(wbb.x, wbb.x); wp[5] = pack2(wbb.y, wbb.y);
        wp[6] = pack2(wbb.z, wbb.z); wp[7] = pack2(wbb.w, wbb.w);
        const ull* xv = (const ull*)&sIn[ic * PXT + px0];
        ull x0 = xv[0], x1 = xv[1], x2 = xv[2], x3 = xv[3];
#pragma unroll
        for (int j = 0; j < 8; ++j) {
            acc[j][0] = ffma2(wp[j], x0, acc[j][0]);
            acc[j][1] = ffma2(wp[j], x1, acc[j][1]);
            acc[j][2] = ffma2(wp[j], x2, acc[j][2]);
            acc[j][3] = ffma2(wp[j], x3, acc[j][3]);
        }
    }
#pragma unroll
    for (int j = 0; j < 8; ++j) {
        long o = (long)(b * OC + oc0 + j) * HW + pix0 + px0;
        float v[8];
#pragma unroll
        for (int k = 0; k < 4; ++k) unpack2(acc[j][k], v[2 * k], v[2 * k + 1]);
        float4 a0 = make_float4(v[0], v[1], v[2], v[3]);
        float4 a1 = make_float4(v[4], v[5], v[6], v[7]);
        if (RES) {
            float4 r0 = *(const float4*)&res[o];
            float4 r1 = *(const float4*)&res[o + 4];
            a0.x += r0.x; a0.y += r0.y; a0.z += r0.z; a0.w += r0.w;
            a1.x += r1.x; a1.y += r1.y; a1.z += r1.z; a1.w += r1.w;
        }
        *(float4*)&out[o] = a0;
        *(float4*)&out[o + 4] = a1;
    }
}

// ---------------- depthwise 3x3 v2: 8 px per thread, vector fast path ----------------
template<int CH>
__global__ void dw3x3_kernel(const float* __restrict__ in, const float* __restrict__ w,
                             float* __restrict__ out)
{
    int p = blockIdx.x * 256 + threadIdx.x;
    int xg = p & 31;
    int y = (p >> 5) & 255;
    int g = p >> 13;              // b*CH + c
    int c = g & (CH - 1);
    int x0 = xg * 8;
    const float* wp = w + c * 9;
    float wr[9];
#pragma unroll
    for (int t = 0; t < 9; ++t) wr[t] = wp[t];
    const float* ip = in + (long)g * HW;
    float r[3][10];
    bool interior = (y > 0) && (y < 255) && (xg > 0) && (xg < 31);
    if (interior) {
#pragma unroll
        for (int rr = 0; rr < 3; ++rr) {
            const float* base = ip + (y - 1 + rr) * 256 + x0;
            float4 a = *(const float4*)base;
            float4 bq = *(const float4*)(base + 4);
            r[rr][0] = base[-1];
            r[rr][1] = a.x; r[rr][2] = a.y; r[rr][3] = a.z; r[rr][4] = a.w;
            r[rr][5] = bq.x; r[rr][6] = bq.y; r[rr][7] = bq.z; r[rr][8] = bq.w;
            r[rr][9] = base[8];
        }
    } else {
#pragma unroll
        for (int rr = 0; rr < 3; ++rr) {
            int iy = y - 1 + rr;
#pragma unroll
            for (int j = 0; j < 10; ++j) {
                int ix = x0 - 1 + j;
                r[rr][j] = (iy >= 0 && iy < 256 && ix >= 0 && ix < 256) ? ip[iy * 256 + ix] : 0.f;
            }
        }
    }
    float acc[8];
#pragma unroll
    for (int q = 0; q < 8; ++q) acc[q] = 0.f;
#pragma unroll
    for (int ky = 0; ky < 3; ++ky)
#pragma unroll
        for (int kx = 0; kx < 3; ++kx) {
            float wv = wr[ky * 3 + kx];
#pragma unroll
            for (int q = 0; q < 8; ++q) acc[q] += wv * r[ky][q + kx];
        }
    float* op = out + (long)g * HW + y * 256 + x0;
    *(float4*)op = make_float4(acc[0], acc[1], acc[2], acc[3]);
    *(float4*)(op + 4) = make_float4(acc[4], acc[5], acc[6], acc[7]);
}

// ---------------- attention stats ----------------
__global__ void attn_stats_kernel(const float* __restrict__ q, const float* __restrict__ k,
                                  float* __restrict__ part)
{
    __shared__ float sQ[16 * 129];
    __shared__ float sK[16 * 129];
    int g = blockIdx.y;
    int b = g >> 2, h = g & 3;
    const float* qb = q + (long)b * 64 * HW + (long)h * 16 * HW;
    const float* kb = k + (long)b * 128 * HW + (long)h * 16 * HW;
    int tid = threadIdx.x;
    int c = tid >> 4, d = tid & 15;
    float accG = 0.f, accQ = 0.f, accK = 0.f;
    int nbase = blockIdx.x * (HW / NCHUNK);
    for (int sub = 0; sub < (HW / NCHUNK) / 128; ++sub) {
        int n0 = nbase + sub * 128;
#pragma unroll
        for (int i = 0; i < 8; ++i) {
            int lin = tid + i * 256;
            int cc = lin >> 7, nn = lin & 127;
            sQ[cc * 129 + nn] = qb[(long)cc * HW + n0 + nn];
            sK[cc * 129 + nn] = kb[(long)cc * HW + n0 + nn];
        }
        __syncthreads();
        const float* qr = sQ + c * 129;
        const float* kr = sK + d * 129;
#pragma unroll 8
        for (int nn = 0; nn < 128; ++nn) accG += qr[nn] * kr[nn];
        if (d == 0) {
#pragma unroll 8
            for (int nn = 0; nn < 128; ++nn) accQ += qr[nn] * qr[nn];
        }
        if (c == 0) {
#pragma unroll 8
            for (int nn = 0; nn < 128; ++nn) accK += kr[nn] * kr[nn];
        }
        __syncthreads();
    }
    float* pp = part + ((long)g * NCHUNK + blockIdx.x) * 288;
    pp[tid] = accG;
    if (d == 0) pp[256 + c] = accQ;
    if (c == 0) pp[272 + d] = accK;
}

// ---------------- finish: softmax + fold W_proj -> M[b][64][64] ----------------
__global__ void attn_finish_kernel(const float* __restrict__ part, const float* __restrict__ wproj,
                                   const float* __restrict__ temp, float* __restrict__ Mout)
{
    int b = blockIdx.x, tid = threadIdx.x;
    __shared__ float sG[4][256];
    __shared__ float sq[4][16], sk[4][16];
    __shared__ float sA[4][16][16];
    for (int h = 0; h < 4; ++h) {
        const float* pp = part + ((long)(b * 4 + h)) * NCHUNK * 288;
        float s = 0.f;
        for (int ch = 0; ch < NCHUNK; ++ch) s += pp[ch * 288 + tid];
        sG[h][tid] = s;
        if (tid < 32) {
            float s2 = 0.f;
            for (int ch = 0; ch < NCHUNK; ++ch) s2 += pp[ch * 288 + 256 + tid];
            if (tid < 16) sq[h][tid] = s2; else sk[h][tid - 16] = s2;
        }
    }
    __syncthreads();
    if (tid < 64) {
        int h = tid >> 4, c = tid & 15;
        float qn = fmaxf(sqrtf(sq[h][c]), 1e-12f);
        float tp = temp[h];
        float lg[16];
        float mx = -1e30f;
#pragma unroll
        for (int d = 0; d < 16; ++d) {
            float kn = fmaxf(sqrtf(sk[h][d]), 1e-12f);
            lg[d] = tp * sG[h][c * 16 + d] / (qn * kn);
            mx = fmaxf(mx, lg[d]);
        }
        float ssum = 0.f;
#pragma unroll
        for (int d = 0; d < 16; ++d) { lg[d] = expf(lg[d] - mx); ssum += lg[d]; }
        float inv = 1.f / ssum;
#pragma unroll
        for (int d = 0; d < 16; ++d) sA[h][c][d] = lg[d] * inv;
    }
    __syncthreads();
    for (int e = tid; e < 4096; e += 256) {
        int oc = e >> 6, j = e & 63, h = j >> 4, d = j & 15;
        float s = 0.f;
#pragma unroll
        for (int r = 0; r < 16; ++r) s += wproj[oc * 64 + h * 16 + r] * sA[h][r][d];
        Mout[b * 4096 + e] = s;
    }
}

// ---------------- dense 3x3 conv v2: oc-paired f32x2, cp.async double-buffered ----------------
// Block: 256 thr, output 64 oc x (4 rows x 64 cols). Thread: 8 oc x 8 px.
// Weights pre-transposed to [(ic*9+t)*64 + oc].
// EPI: 0 none, 1 gelu, 2 mix out=aux1*sigmoid(acc)+aux2, 3 acc+aux1
template<int EPI>
__global__ void __launch_bounds__(256, 2)
conv3x3_kernel(const float* __restrict__ in, const float* __restrict__ wT,
               const float* __restrict__ aux1, const float* __restrict__ aux2,
               float* __restrict__ out)
{
    __shared__ float sx[2][4][6][68];
    __shared__ float4 sw4[2][576];      // [ic_l][tap][oc] as float4

    int tid = threadIdx.x;
    int bx = blockIdx.x;
    int b = blockIdx.y;
    int tx = bx & 3, ty = bx >> 2;
    int x0 = tx * 64, y0 = ty * 4;
    int ocg = tid >> 5;
    int pxg = tid & 31;
    int row = pxg >> 3;
    int colg = pxg & 7;
    int oc0 = ocg * 8;

    const float* inb = in + (long)b * (64 * HW);

    // ---- staging lambda-ish (macro by hand) ----
    // input chunk icb covers ic = icb*4 .. +3
#define STAGE(ICB, BUF) do { \
        int icBase = (ICB) * 4; \
        for (int idx = tid; idx < 1632; idx += 256) { \
            int ic_l = idx / 408; \
            int rem = idx - ic_l * 408; \
            int ry = rem / 68; \
            int cx = rem - ry * 68; \
            int gy = y0 - 1 + ry; \
            int gx = x0 - 2 + cx; \
            bool ok = (gy >= 0) && (gy < 256) && (gx >= 0) && (gx < 256); \
            const float* gsrc = ok ? (inb + (long)(icBase + ic_l) * HW + gy * 256 + gx) : inb; \
            cpa4(smaddr(&sx[BUF][ic_l][ry][cx]), gsrc, ok); \
        } \
        const float4* wsrc = (const float4*)(wT + (long)icBase * 576); \
        for (int idx = tid; idx < 576; idx += 256) { \
            cpa16(smaddr(&sw4[BUF][idx]), wsrc + idx); \
        } \
    } while (0)

    ull acc[4][8];
#pragma unroll
    for (int j = 0; j < 4; ++j)
#pragma unroll
        for (int p2 = 0; p2 < 8; ++p2) acc[j][p2] = 0ull;

    STAGE(0, 0);
    cpa_commit();

    for (int icb = 0; icb < 16; ++icb) {
        int buf = icb & 1;
        if (icb < 15) {
            STAGE(icb + 1, (icb + 1) & 1);
            cpa_commit();
            cpa_wait1();
        } else {
            cpa_wait0();
        }
        __syncthreads();
        const float* swf = (const float*)sw4[buf];
#pragma unroll
        for (int ic_l = 0; ic_l < 4; ++ic_l) {
#pragma unroll
            for (int ky = 0; ky < 3; ++ky) {
                const float* xs = &sx[buf][ic_l][row + ky][colg * 8 + 1];
                ull xp[10];
#pragma unroll
                for (int j = 0; j < 10; ++j) {
                    float xv = xs[j];
                    xp[j] = pack2(xv, xv);
                }
#pragma unroll
                for (int kx = 0; kx < 3; ++kx) {
                    const ull* wp = (const ull*)&swf[(ic_l * 9 + ky * 3 + kx) * 64 + oc0];
                    ull w0 = wp[0], w1 = wp[1], w2 = wp[2], w3 = wp[3];
#pragma unroll
                    for (int p2 = 0; p2 < 8; ++p2) {
                        ull xv = xp[p2 + kx];
                        acc[0][p2] = ffma2(w0, xv, acc[0][p2]);
                        acc[1][p2] = ffma2(w1, xv, acc[1][p2]);
                        acc[2][p2] = ffma2(w2, xv, acc[2][p2]);
                        acc[3][p2] = ffma2(w3, xv, acc[3][p2]);
                    }
                }
            }
        }
        __syncthreads();
    }
#undef STAGE

    // ---- epilogue ----
    float v[8][8];
#pragma unroll
    for (int j = 0; j < 4; ++j)
#pragma unroll
        for (int p2 = 0; p2 < 8; ++p2)
            unpack2(acc[j][p2], v[2 * j][p2], v[2 * j + 1][p2]);

    long base = (long)(b * 64 + oc0) * HW + (y0 + row) * 256 + x0 + colg * 8;
#pragma unroll
    for (int ol = 0; ol < 8; ++ol) {
        long o = base + (long)ol * HW;
        float* vv = v[ol];
        if (EPI == 1) {
#pragma unroll
            for (int k = 0; k < 8; ++k) vv[k] = gelu_f(vv[k]);
        } else if (EPI == 2) {
            float4 y0v = *(const float4*)&aux1[o];
            float4 y1v = *(const float4*)&aux1[o + 4];
            float4 a0v = *(const float4*)&aux2[o];
            float4 a1v = *(const float4*)&aux2[o + 4];
            float ya[8] = {y0v.x, y0v.y, y0v.z, y0v.w, y1v.x, y1v.y, y1v.z, y1v.w};
            float aa[8] = {a0v.x, a0v.y, a0v.z, a0v.w, a1v.x, a1v.y, a1v.z, a1v.w};
#pragma unroll
            for (int k = 0; k < 8; ++k) {
                float s = 1.f / (1.f + expf(-vv[k]));
                vv[k] = ya[k] * s + aa[k];
            }
        } else if (EPI == 3) {
            float4 r0 = *(const float4*)&aux1[o];
            float4 r1 = *(const float4*)&aux1[o + 4];
            vv[0] += r0.x; vv[1] += r0.y; vv[2] += r0.z; vv[3] += r0.w;
            vv[4] += r1.x; vv[5] += r1.y; vv[6] += r1.z; vv[7] += r1.w;
        }
        *(float4*)&out[o] = make_float4(vv[0], vv[1], vv[2], vv[3]);
        *(float4*)&out[o + 4] = make_float4(vv[4], vv[5], vv[6], vv[7]);
    }
}

extern "C" void kernel_launch(void* const* d_in, const int* in_sizes, int n_in,
                              void* d_out, int out_size)
{
    const float* x       = (const float*)d_in[0];
    const float* ref     = (const float*)d_in[1];
    const float* ln1w    = (const float*)d_in[2];
    const float* ln1b    = (const float*)d_in[3];
    const float* ln2w    = (const float*)d_in[4];
    const float* ln2b    = (const float*)d_in[5];
    const float* ln3w    = (const float*)d_in[6];
    const float* ln3b    = (const float*)d_in[7];
    const float* w_kv    = (const float*)d_in[8];
    const float* w_kv_dw = (const float*)d_in[9];
    const float* w_q     = (const float*)d_in[10];
    const float* w_q_dw  = (const float*)d_in[11];
    const float* w_proj  = (const float*)d_in[12];
    const float* temp    = (const float*)d_in[13];
    const float* w_add1  = (const float*)d_in[14];
    const float* w_add2  = (const float*)d_in[15];
    const float* w_mul1  = (const float*)d_in[16];
    const float* w_fuse  = (const float*)d_in[17];
    float* out = (float*)d_out;

    float* pool = nullptr;
    cudaGetSymbolAddress((void**)&pool, g_pool);
    const long SZ = 16777216L, SZ2 = 33554432L;
    float* kv0  = pool;
    float* kv1  = pool + SZ2;
    float* bufA = pool + 2 * SZ2;
    float* bufB = bufA + SZ;
    float* bufC = bufB + SZ;
    float* bufD = bufC + SZ;
    float* bufE = bufD + SZ;
    float* x1   = bufE + SZ;
    float* Mb   = x1 + SZ;
    float* part = Mb + 16384;
    float* wTa1 = part + 294912;
    float* wTa2 = wTa1 + 36864;
    float* wTm  = wTa2 + 36864;
    float* wTf  = wTm + 36864;

    // weight transposes (tiny, run first)
    wtrans_kernel<<<144, 256>>>(w_add1, wTa1);
    wtrans_kernel<<<144, 256>>>(w_add2, wTa2);
    wtrans_kernel<<<144, 256>>>(w_mul1, wTm);
    wtrans_kernel<<<144, 256>>>(w_fuse, wTf);

    // ---- Attention branch ----
    conv1x1_kernel<128, true, false, false><<<dim3(1024, 4), 128>>>(ref, w_kv, ln1w, ln1b, nullptr, kv0, 64 * HW, 0);
    conv1x1_kernel<64,  true, false, false><<<dim3(512, 4), 128>>>(x, w_q, ln3w, ln3b, nullptr, bufC, 64 * HW, 0);
    dw3x3_kernel<128><<<16384, 256>>>(kv0,  w_kv_dw, kv1);
    dw3x3_kernel<64><<<8192, 256>>>(bufC, w_q_dw, bufD);
    attn_stats_kernel<<<dim3(NCHUNK, 16), 256>>>(bufD, kv1, part);
    attn_finish_kernel<<<4, 256>>>(part, w_proj, temp, Mb);
    conv1x1_kernel<64, false, true, true><<<dim3(512, 4), 128>>>(kv1, Mb, nullptr, nullptr, x, x1, 128 * HW, 64);

    // ---- SFM branch ----
    ln_kernel<<<1024, 256>>>(x1, ln2w, ln2b, bufA);                                     // y
    conv3x3_kernel<1><<<dim3(256, 4), 256>>>(bufA, wTa1, nullptr, nullptr, bufB);       // ga1
    conv3x3_kernel<0><<<dim3(256, 4), 256>>>(bufB, wTa2, nullptr, nullptr, bufC);       // x_add
    conv3x3_kernel<1><<<dim3(256, 4), 256>>>(bufA, wTm, nullptr, nullptr, bufD);        // gm1
    conv3x3_kernel<2><<<dim3(256, 4), 256>>>(bufD, wTm, bufA, bufC, bufE);              // z
    conv3x3_kernel<3><<<dim3(256, 4), 256>>>(bufE, wTf, x1, nullptr, out);              // out
}